// round 11
// baseline (speedup 1.0000x reference)
#include <cuda_runtime.h>
#include <cuda_fp16.h>
#include <cstdint>
#include <cstddef>

// ---------------------------------------------------------------------------
//   u    [128, 512, 512]  f32   -> A fp16 [65536, 512]
//   W_im [2048, 512]      f32   -> B fp16 [2048, 512], rows PERMUTED so that
//        new col n holds orig row  8*(n>>4) + 2*((n&7)>>1) + ((n>>3)&1) + (n&1)*1024
//   FUSED kernel: CTA = (batch b, chunk of 256 GEMM cols = 128 channels).
//        For each of 4 l-tiles (128 rows): 3-stage cp.async GEMM (K=512),
//        fused epilogue s = tanh((c1+b_c1)/5)*5 + io + b_io -> SMEM,
//        then 128 sequential scan steps from SMEM (hf/hs carried in regs).
//   No g_s global scratch at all.
// ---------------------------------------------------------------------------

#define NROWS   65536
#define KIN     512
#define NOUT    2048
#define MEMSZ   1024

__device__ __half g_A[(size_t)NROWS * KIN];     // 64 MB
__device__ __half g_B[(size_t)NOUT * KIN];      //  2 MB (permuted)

// ----------------------------- fast activations -----------------------------

__device__ __forceinline__ float ftanh(float x) {
    float t = __expf(2.0f * x);
    return 1.0f - __fdividef(2.0f, t + 1.0f);
}
__device__ __forceinline__ float fsigmoid(float x) {
    return __fdividef(1.0f, 1.0f + __expf(-x));
}

// ------------------------------- PTX helpers --------------------------------

__device__ __forceinline__ uint32_t smem_u32(const void* p) {
    uint32_t a;
    asm("{ .reg .u64 t; cvta.to.shared.u64 t, %1; cvt.u32.u64 %0, t; }"
        : "=r"(a) : "l"(p));
    return a;
}

#define CP_ASYNC16(saddr, gptr) \
    asm volatile("cp.async.cg.shared.global [%0], [%1], 16;" \
                 :: "r"(saddr), "l"(gptr) : "memory")
#define CP_COMMIT() asm volatile("cp.async.commit_group;" ::: "memory")
#define CP_WAIT1()  asm volatile("cp.async.wait_group 1;" ::: "memory")

#define LDMATRIX_X4(r0, r1, r2, r3, addr) \
    asm volatile("ldmatrix.sync.aligned.m8n8.x4.shared.b16 {%0,%1,%2,%3}, [%4];" \
                 : "=r"(r0), "=r"(r1), "=r"(r2), "=r"(r3) : "r"(addr))

#define MMA16816(d, a, b0, b1) \
    asm volatile("mma.sync.aligned.m16n8k16.row.col.f32.f16.f16.f32 " \
                 "{%0,%1,%2,%3}, {%4,%5,%6,%7}, {%8,%9}, {%0,%1,%2,%3};" \
                 : "+f"((d)[0]), "+f"((d)[1]), "+f"((d)[2]), "+f"((d)[3]) \
                 : "r"((a)[0]), "r"((a)[1]), "r"((a)[2]), "r"((a)[3]), \
                   "r"(b0), "r"(b1))

__device__ __forceinline__ uint32_t swz(uint32_t off) {
    return off ^ ((off >> 3) & 0x70);
}

// ------------------------------- convert kernels ----------------------------

__global__ void cvt_a_kernel(const float4* __restrict__ src, __half2* __restrict__ dst,
                             size_t n4) {
    size_t i = (size_t)blockIdx.x * blockDim.x + threadIdx.x;
    if (i >= n4) return;
    float4 v = src[i];
    dst[2 * i]     = __floats2half2_rn(v.x, v.y);
    dst[2 * i + 1] = __floats2half2_rn(v.z, v.w);
}

// W conversion with fragment-pair permutation:
// new col n <- orig row 8*(n>>4) + 2*((n&7)>>1) + ((n>>3)&1) + (n&1)*MEMSZ
__global__ void cvt_w_kernel(const float* __restrict__ W) {
    int i = blockIdx.x * 256 + threadIdx.x;       // over 2048 * 128 float4s
    int n  = i >> 7;
    int k4 = i & 127;
    int orig = 8 * (n >> 4) + 2 * ((n & 7) >> 1) + ((n >> 3) & 1) + (n & 1) * MEMSZ;
    float4 v = reinterpret_cast<const float4*>(W + (size_t)orig * KIN)[k4];
    __half2* d = reinterpret_cast<__half2*>(g_B + (size_t)n * KIN) + 2 * k4;
    d[0] = __floats2half2_rn(v.x, v.y);
    d[1] = __floats2half2_rn(v.z, v.w);
}

// ----------------------------- fused GEMM + scan -----------------------------
// CTA: batch b (blockIdx.y), chunk c (blockIdx.x) of 256 GEMM cols.
// l-tile 128 rows, k-tile 64 -> flat 32-step pipeline (4 lt x 8 kt).
// SMEM: 3 stages x (A 16KB + B 32KB) + s buffer 128x128 f32 (64KB).

#define NLT        4
#define NKT        8
#define NSTEPS     (NLT * NKT)        // 32
#define STAGE_SZ   49152              // A 16384 + B 32768
#define SM_S       (3 * STAGE_SZ)     // 147456
#define FUSED_SMEM (SM_S + 128 * 128 * 4)   // 212992

__device__ __forceinline__ void load_stage_f(uint32_t sb, int stage, int t,
                                             const char* gA_b, const char* gB_c,
                                             int tid) {
    uint32_t sA = sb + stage * STAGE_SZ;
    uint32_t sB = sA + 16384;
    int lt = t >> 3, kt = t & 7;
    const char* a_src = gA_b + (size_t)lt * (128 * 1024) + kt * 128;
    const char* b_src = gB_c + kt * 128;
    #pragma unroll
    for (int it = 0; it < 4; it++) {              // A: 128 rows x 8 x 16B
        int i = tid + it * 256;
        int r = i >> 3, j = i & 7;
        uint32_t off = swz((uint32_t)(r * 128 + j * 16));
        CP_ASYNC16(sA + off, a_src + (size_t)r * 1024 + j * 16);
    }
    #pragma unroll
    for (int it = 0; it < 8; it++) {              // B: 256 rows x 8 x 16B
        int i = tid + it * 256;
        int r = i >> 3, j = i & 7;
        uint32_t off = swz((uint32_t)(r * 128 + j * 16));
        CP_ASYNC16(sB + off, b_src + (size_t)r * 1024 + j * 16);
    }
}

__global__ void __launch_bounds__(256, 1) fused_kernel(const float* __restrict__ b_im,
                                                       const float* __restrict__ h0,
                                                       float* __restrict__ out) {
    extern __shared__ char smem[];
    uint32_t sb = smem_u32(smem);
    float* s_sm = reinterpret_cast<float*>(smem + SM_S);
    int tid  = threadIdx.x;
    int lane = tid & 31;
    int warp = tid >> 5;
    int wm = warp & 1;                  // 0..1 (64 rows)
    int wn = warp >> 1;                 // 0..3 (64 cols)

    int chunk = blockIdx.x;             // 0..7
    int b     = blockIdx.y;             // 0..127

    const char* gA_b = (const char*)g_A + (size_t)b * 512 * 1024;       // 512 rows x 1KB
    const char* gB_c = (const char*)g_B + (size_t)chunk * 256 * 1024;   // 256 rows x 1KB

    // scan carry (threads 0..127 own channel chunk*128 + tid)
    float hf = 0.0f, hs = 0.0f;
    if (tid < 128) {
        int m_glob = chunk * 128 + tid;
        hf = h0[(size_t)b * MEMSZ + m_glob];
        hs = h0[(size_t)128 * MEMSZ + (size_t)b * MEMSZ + m_glob];
    }

    float acc[4][8][4];
    #pragma unroll
    for (int mi = 0; mi < 4; mi++)
        #pragma unroll
        for (int ni = 0; ni < 8; ni++)
            #pragma unroll
            for (int e = 0; e < 4; e++) acc[mi][ni][e] = 0.0f;

    uint32_t a_row = (uint32_t)(wm * 64 + (lane & 15));
    uint32_t a_kx  = (uint32_t)((lane >> 4) << 4);
    uint32_t b_row = (uint32_t)(wn * 64 + ((lane >> 4) << 3) + (lane & 7));
    uint32_t b_kx  = (uint32_t)(((lane >> 3) & 1) << 4);

    load_stage_f(sb, 0, 0, gA_b, gB_c, tid); CP_COMMIT();
    load_stage_f(sb, 1, 1, gA_b, gB_c, tid); CP_COMMIT();

    for (int t = 0; t < NSTEPS; t++) {
        CP_WAIT1();
        __syncthreads();
        if (t + 2 < NSTEPS)
            load_stage_f(sb, (t + 2) % 3, t + 2, gA_b, gB_c, tid);
        CP_COMMIT();

        uint32_t sA = sb + (t % 3) * STAGE_SZ;
        uint32_t sB = sA + 16384;

        #pragma unroll
        for (int ks = 0; ks < 4; ks++) {
            uint32_t a[4][4];
            #pragma unroll
            for (int mi = 0; mi < 4; mi++) {
                uint32_t off = (a_row + mi * 16) * 128 + ks * 32 + a_kx;
                LDMATRIX_X4(a[mi][0], a[mi][1], a[mi][2], a[mi][3], sA + swz(off));
            }
            uint32_t bf[4][4];
            #pragma unroll
            for (int ni2 = 0; ni2 < 4; ni2++) {
                uint32_t off = (b_row + ni2 * 16) * 128 + ks * 32 + b_kx;
                LDMATRIX_X4(bf[ni2][0], bf[ni2][1], bf[ni2][2], bf[ni2][3], sB + swz(off));
            }
            #pragma unroll
            for (int mi = 0; mi < 4; mi++) {
                #pragma unroll
                for (int ni2 = 0; ni2 < 4; ni2++) {
                    MMA16816(acc[mi][ni2 * 2],     a[mi], bf[ni2][0], bf[ni2][1]);
                    MMA16816(acc[mi][ni2 * 2 + 1], a[mi], bf[ni2][2], bf[ni2][3]);
                }
            }
        }

        if ((t & 7) == 7) {
            int lt = t >> 3;
            // ---- fused epilogue -> SMEM s[l_local][ch_local] ----
            int r_loc  = wm * 64 + (lane >> 2);
            int mb_loc = wn * 32 + (lane & 3) * 2;
            #pragma unroll
            for (int tt = 0; tt < 4; tt++) {
                int ml = mb_loc + 8 * tt;
                int mg = chunk * 128 + ml;
                float bc0 = __ldg(b_im + mg);
                float bi0 = __ldg(b_im + mg + MEMSZ);
                float bc1 = __ldg(b_im + mg + 1);
                float bi1 = __ldg(b_im + mg + 1 + MEMSZ);
                #pragma unroll
                for (int mi = 0; mi < 4; mi++) {
                    int l = r_loc + mi * 16;
                    float* aE = acc[mi][2 * tt];
                    float* aO = acc[mi][2 * tt + 1];
                    float2 v0, v1;
                    v0.x = ftanh((aE[0] + bc0) * 0.2f) * 5.0f + aE[1] + bi0;
                    v0.y = ftanh((aO[0] + bc1) * 0.2f) * 5.0f + aO[1] + bi1;
                    v1.x = ftanh((aE[2] + bc0) * 0.2f) * 5.0f + aE[3] + bi0;
                    v1.y = ftanh((aO[2] + bc1) * 0.2f) * 5.0f + aO[3] + bi1;
                    *reinterpret_cast<float2*>(s_sm + l * 128 + ml)       = v0;
                    *reinterpret_cast<float2*>(s_sm + (l + 8) * 128 + ml) = v1;
                    #pragma unroll
                    for (int e = 0; e < 4; e++) { aE[e] = 0.0f; aO[e] = 0.0f; }
                }
            }
            __syncthreads();
            // ---- scan 128 steps from SMEM (threads 0..127) ----
            if (tid < 128) {
                float* o = out + ((size_t)b * 512 + (size_t)lt * 128) * MEMSZ
                               + chunk * 128 + tid;
                #pragma unroll 8
                for (int l = 0; l < 128; l++) {
                    float sv  = s_sm[l * 128 + tid];
                    float d   = hs + 0.4f;
                    float arg = sv + 4.0f * hf - 7.0f * d * d;
                    float hfn = ftanh(arg);
                    float eps = 0.9f + 0.9f * fsigmoid((hf - 0.5f) * 10.0f);
                    hs = (1.0f - eps) * hs + eps * hf;
                    hf = hfn;
                    o[(size_t)l * MEMSZ] = hfn;
                }
            }
            __syncthreads();
        }
    }

    // hf_last
    if (tid < 128) {
        out[(size_t)128 * 512 * MEMSZ + (size_t)b * MEMSZ + chunk * 128 + tid] = hf;
    }
}

// ------------------------------ kernel_launch --------------------------------

extern "C" void kernel_launch(void* const* d_in, const int* in_sizes, int n_in,
                              void* d_out, int out_size) {
    const float* u    = (const float*)d_in[0];
    const float* h0   = (const float*)d_in[1];
    const float* W_im = (const float*)d_in[2];
    const float* b_im = (const float*)d_in[3];
    float* out = (float*)d_out;
    (void)in_sizes; (void)n_in; (void)out_size;

    static int smem_set = 0;
    if (!smem_set) {
        cudaFuncSetAttribute(fused_kernel,
                             cudaFuncAttributeMaxDynamicSharedMemorySize, FUSED_SMEM);
        smem_set = 1;
    }

    // 1) fp16 conversions (W permuted)
    {
        __half* dA;
        cudaGetSymbolAddress((void**)&dA, g_A);
        size_t nA4 = (size_t)NROWS * KIN / 4;
        cvt_w_kernel<<<(NOUT * (KIN / 4)) / 256, 256>>>(W_im);
        cvt_a_kernel<<<(unsigned)((nA4 + 255) / 256), 256>>>(
            (const float4*)u, (__half2*)dA, nA4);
    }

    // 2) fused GEMM + epilogue + scan -> out
    dim3 fgrid(8, 128);
    fused_kernel<<<fgrid, 256, FUSED_SMEM>>>(b_im, h0, out);
}

// round 15
// speedup vs baseline: 1.3230x; 1.3230x over previous
#include <cuda_runtime.h>
#include <cuda_fp16.h>
#include <cstdint>
#include <cstddef>

// ---------------------------------------------------------------------------
//   u    [128, 512, 512]  f32   -> A fp16 [65536, 512]
//   W_im [2048, 512]      f32   -> B fp16 [2048, 512], rows PERMUTED so that
//        new col n holds orig row  8*(n>>4) + 2*((n&7)>>1) + ((n>>3)&1) + (n&1)*1024
//        => in each mma fragment pair (ni=2t, 2t+1) a thread holds the fused
//           (c1, io) pairs of channels m and m+1  -> coalesced float2 stores
//   epilogue fuses: s = tanh((c1+b_c1)/5)*5 + io + b_io -> g_s f32 [65536,1024]
//   scan over l (512 steps) per (b,m) channel, prefetch-pipelined loads.
// ---------------------------------------------------------------------------

#define NROWS   65536
#define KIN     512
#define NOUT    2048
#define MEMSZ   1024

__device__ __half g_A[(size_t)NROWS * KIN];     // 64 MB
__device__ __half g_B[(size_t)NOUT * KIN];      //  2 MB (permuted)
__device__ float  g_s[(size_t)NROWS * MEMSZ];   // 256 MB fused scratch

// ----------------------------- fast activations -----------------------------

__device__ __forceinline__ float ftanh(float x) {
    float t = __expf(2.0f * x);
    return 1.0f - __fdividef(2.0f, t + 1.0f);
}
__device__ __forceinline__ float fsigmoid(float x) {
    return __fdividef(1.0f, 1.0f + __expf(-x));
}

// ------------------------------- PTX helpers --------------------------------

__device__ __forceinline__ uint32_t smem_u32(const void* p) {
    uint32_t a;
    asm("{ .reg .u64 t; cvta.to.shared.u64 t, %1; cvt.u32.u64 %0, t; }"
        : "=r"(a) : "l"(p));
    return a;
}

#define CP_ASYNC16(saddr, gptr) \
    asm volatile("cp.async.cg.shared.global [%0], [%1], 16;" \
                 :: "r"(saddr), "l"(gptr) : "memory")
#define CP_COMMIT() asm volatile("cp.async.commit_group;" ::: "memory")
#define CP_WAIT1()  asm volatile("cp.async.wait_group 1;" ::: "memory")

#define LDMATRIX_X4(r0, r1, r2, r3, addr) \
    asm volatile("ldmatrix.sync.aligned.m8n8.x4.shared.b16 {%0,%1,%2,%3}, [%4];" \
                 : "=r"(r0), "=r"(r1), "=r"(r2), "=r"(r3) : "r"(addr))

#define MMA16816(d, a, b0, b1) \
    asm volatile("mma.sync.aligned.m16n8k16.row.col.f32.f16.f16.f32 " \
                 "{%0,%1,%2,%3}, {%4,%5,%6,%7}, {%8,%9}, {%0,%1,%2,%3};" \
                 : "+f"((d)[0]), "+f"((d)[1]), "+f"((d)[2]), "+f"((d)[3]) \
                 : "r"((a)[0]), "r"((a)[1]), "r"((a)[2]), "r"((a)[3]), \
                   "r"(b0), "r"(b1))

__device__ __forceinline__ uint32_t swz(uint32_t off) {
    return off ^ ((off >> 3) & 0x70);
}

// ------------------------------- convert kernels ----------------------------

__global__ void cvt_a_kernel(const float4* __restrict__ src, __half2* __restrict__ dst,
                             size_t n4) {
    size_t i = (size_t)blockIdx.x * blockDim.x + threadIdx.x;
    if (i >= n4) return;
    float4 v = src[i];
    dst[2 * i]     = __floats2half2_rn(v.x, v.y);
    dst[2 * i + 1] = __floats2half2_rn(v.z, v.w);
}

// W conversion with fragment-pair permutation:
// new col n <- orig row 8*(n>>4) + 2*((n&7)>>1) + ((n>>3)&1) + (n&1)*MEMSZ
__global__ void cvt_w_kernel(const float* __restrict__ W) {
    int i = blockIdx.x * 256 + threadIdx.x;       // over 2048 * 128 float4s
    int n  = i >> 7;
    int k4 = i & 127;
    int orig = 8 * (n >> 4) + 2 * ((n & 7) >> 1) + ((n >> 3) & 1) + (n & 1) * MEMSZ;
    float4 v = reinterpret_cast<const float4*>(W + (size_t)orig * KIN)[k4];
    __half2* d = reinterpret_cast<__half2*>(g_B + (size_t)n * KIN) + 2 * k4;
    d[0] = __floats2half2_rn(v.x, v.y);
    d[1] = __floats2half2_rn(v.z, v.w);
}

// --------------------------------- GEMM -------------------------------------
// CTA 128x128, k-tile 64, 3-stage cp.async pipeline, 4 warps (2x2),
// warp tile 64x64: per k16 step 8 LDSM.x4 feed 32 HMMA.  (Proven R9 body.)

#define KT_BYTES   128
#define STAGE_SZ   32768
#define GEMM_SMEM  (3 * STAGE_SZ)
#define NKT        (KIN / 64)         // 8

__device__ __forceinline__ void load_stage(uint32_t sb, int stage, int kt,
                                           const char* gA, const char* gB, int tid) {
    uint32_t sA = sb + stage * STAGE_SZ;
    uint32_t sB = sA + 16384;
    const char* a_src = gA + kt * KT_BYTES;
    const char* b_src = gB + kt * KT_BYTES;
    #pragma unroll
    for (int it = 0; it < 8; it++) {
        int i = tid + it * 128;
        int r = i >> 3, j = i & 7;
        uint32_t off = swz((uint32_t)(r * 128 + j * 16));
        CP_ASYNC16(sA + off, a_src + (size_t)r * 1024 + j * 16);
    }
    #pragma unroll
    for (int it = 0; it < 8; it++) {
        int i = tid + it * 128;
        int r = i >> 3, j = i & 7;
        uint32_t off = swz((uint32_t)(r * 128 + j * 16));
        CP_ASYNC16(sB + off, b_src + (size_t)r * 1024 + j * 16);
    }
}

__global__ void __launch_bounds__(128, 2) gemm_kernel(const float* __restrict__ b_im) {
    extern __shared__ char smem[];
    uint32_t sb = smem_u32(smem);
    int tid  = threadIdx.x;
    int lane = tid & 31;
    int warp = tid >> 5;
    int wm = warp >> 1;
    int wn = warp & 1;

    size_t m0 = (size_t)blockIdx.y * 128;
    int    n0 = (int)blockIdx.x * 128;

    const char* gA = (const char*)g_A + m0 * (KIN * 2);
    const char* gB = (const char*)g_B + (size_t)n0 * (KIN * 2);

    float acc[4][8][4];
    #pragma unroll
    for (int mi = 0; mi < 4; mi++)
        #pragma unroll
        for (int ni = 0; ni < 8; ni++)
            #pragma unroll
            for (int e = 0; e < 4; e++) acc[mi][ni][e] = 0.0f;

    uint32_t a_row = (uint32_t)(wm * 64 + (lane & 15));
    uint32_t a_kx  = (uint32_t)((lane >> 4) << 4);
    uint32_t b_row = (uint32_t)(wn * 64 + ((lane >> 4) << 3) + (lane & 7));
    uint32_t b_kx  = (uint32_t)(((lane >> 3) & 1) << 4);

    load_stage(sb, 0, 0, gA, gB, tid); CP_COMMIT();
    load_stage(sb, 1, 1, gA, gB, tid); CP_COMMIT();

    for (int kt = 0; kt < NKT; kt++) {
        CP_WAIT1();
        __syncthreads();
        if (kt + 2 < NKT) load_stage(sb, (kt + 2) % 3, kt + 2, gA, gB, tid);
        CP_COMMIT();

        uint32_t sA = sb + (kt % 3) * STAGE_SZ;
        uint32_t sB = sA + 16384;

        #pragma unroll
        for (int ks = 0; ks < 4; ks++) {
            uint32_t a[4][4];
            #pragma unroll
            for (int mi = 0; mi < 4; mi++) {
                uint32_t off = (a_row + mi * 16) * 128 + ks * 32 + a_kx;
                LDMATRIX_X4(a[mi][0], a[mi][1], a[mi][2], a[mi][3], sA + swz(off));
            }
            uint32_t b[4][4];
            #pragma unroll
            for (int ni2 = 0; ni2 < 4; ni2++) {
                uint32_t off = (b_row + ni2 * 16) * 128 + ks * 32 + b_kx;
                LDMATRIX_X4(b[ni2][0], b[ni2][1], b[ni2][2], b[ni2][3], sB + swz(off));
            }
            #pragma unroll
            for (int mi = 0; mi < 4; mi++) {
                #pragma unroll
                for (int ni2 = 0; ni2 < 4; ni2++) {
                    MMA16816(acc[mi][ni2 * 2],     a[mi], b[ni2][0], b[ni2][1]);
                    MMA16816(acc[mi][ni2 * 2 + 1], a[mi], b[ni2][2], b[ni2][3]);
                }
            }
        }
    }

    // Fused epilogue: fragment pair (2t, 2t+1) => channels m, m+1 per thread;
    // coalesced float2 stores.
    int r_base = (int)m0 + wm * 64 + (lane >> 2);
    int Mb = (n0 >> 1) + wn * 32 + (lane & 3) * 2;
    #pragma unroll
    for (int t = 0; t < 4; t++) {
        int m = Mb + 8 * t;
        float bc0 = __ldg(b_im + m);
        float bi0 = __ldg(b_im + m + MEMSZ);
        float bc1 = __ldg(b_im + m + 1);
        float bi1 = __ldg(b_im + m + 1 + MEMSZ);
        #pragma unroll
        for (int mi = 0; mi < 4; mi++) {
            int row = r_base + mi * 16;
            float* aE = acc[mi][2 * t];
            float* aO = acc[mi][2 * t + 1];
            float2 v0, v1;
            v0.x = ftanh((aE[0] + bc0) * 0.2f) * 5.0f + aE[1] + bi0;
            v0.y = ftanh((aO[0] + bc1) * 0.2f) * 5.0f + aO[1] + bi1;
            v1.x = ftanh((aE[2] + bc0) * 0.2f) * 5.0f + aE[3] + bi0;
            v1.y = ftanh((aO[2] + bc1) * 0.2f) * 5.0f + aO[3] + bi1;
            *reinterpret_cast<float2*>(g_s + (size_t)row * MEMSZ + m)       = v0;
            *reinterpret_cast<float2*>(g_s + (size_t)(row + 8) * MEMSZ + m) = v1;
        }
    }
}

// --------------------------------- scan -------------------------------------
// Prefetch-pipelined: group g+1's 16 loads are issued before group g's
// dependent-chain compute (~900 cyc), fully hiding ~577-cyc DRAM latency.

#define PF 16

__global__ void __launch_bounds__(256) scan_kernel(const float* __restrict__ h0,
                                                   float* __restrict__ out) {
    int idx = blockIdx.x * 256 + threadIdx.x;      // 0 .. 131071
    int b = idx >> 10;
    int m = idx & 1023;

    float hf = h0[(size_t)b * MEMSZ + m];
    float hs = h0[(size_t)128 * MEMSZ + (size_t)b * MEMSZ + m];

    const float* e = g_s + (size_t)b * 512 * MEMSZ + m;
    float* o = out + (size_t)b * 512 * MEMSZ + m;

    float pre[PF];
    #pragma unroll
    for (int i = 0; i < PF; i++) pre[i] = e[(size_t)i * MEMSZ];
    const float* ep = e + (size_t)PF * MEMSZ;

    for (int g = 0; g < 512; g += PF) {
        float cur[PF];
        #pragma unroll
        for (int i = 0; i < PF; i++) cur[i] = pre[i];

        if (g + PF < 512) {
            #pragma unroll
            for (int i = 0; i < PF; i++) pre[i] = ep[(size_t)i * MEMSZ];
            ep += (size_t)PF * MEMSZ;
        }

        #pragma unroll
        for (int i = 0; i < PF; i++) {
            float d   = hs + 0.4f;
            float arg = cur[i] + 4.0f * hf - 7.0f * d * d;
            float hfn = ftanh(arg);
            float eps = 0.9f + 0.9f * fsigmoid((hf - 0.5f) * 10.0f);
            hs = (1.0f - eps) * hs + eps * hf;
            hf = hfn;
            o[(size_t)(g + i) * MEMSZ] = hfn;
        }
    }
    out[(size_t)128 * 512 * MEMSZ + (size_t)b * MEMSZ + m] = hf;
}

// ------------------------------ kernel_launch --------------------------------

extern "C" void kernel_launch(void* const* d_in, const int* in_sizes, int n_in,
                              void* d_out, int out_size) {
    const float* u    = (const float*)d_in[0];
    const float* h0   = (const float*)d_in[1];
    const float* W_im = (const float*)d_in[2];
    const float* b_im = (const float*)d_in[3];
    float* out = (float*)d_out;
    (void)in_sizes; (void)n_in; (void)out_size;

    static int smem_set = 0;
    if (!smem_set) {
        cudaFuncSetAttribute(gemm_kernel,
                             cudaFuncAttributeMaxDynamicSharedMemorySize, GEMM_SMEM);
        smem_set = 1;
    }

    // 1) fp16 conversions (W permuted)
    {
        __half* dA;
        cudaGetSymbolAddress((void**)&dA, g_A);
        size_t nA4 = (size_t)NROWS * KIN / 4;
        cvt_w_kernel<<<(NOUT * (KIN / 4)) / 256, 256>>>(W_im);
        cvt_a_kernel<<<(unsigned)((nA4 + 255) / 256), 256>>>(
            (const float4*)u, (__half2*)dA, nA4);
    }

    // 2) GEMM + fused bias/tanh/sum epilogue -> g_s
    dim3 ggrid(NOUT / 128, NROWS / 128);
    gemm_kernel<<<ggrid, 128, GEMM_SMEM>>>(b_im);

    // 3) sequential scan -> out
    scan_kernel<<<(128 * MEMSZ) / 256, 256>>>(h0, out);
}